// round 8
// baseline (speedup 1.0000x reference)
#include <cuda_runtime.h>
#include <math.h>

#define N_NODES  100000
#define N_EDGES  1000000
#define N_GRAPHS 2048
#define F_IN     78
#define DIM      32
#define T_DIM    208
#define H1       170
#define H2       128
#define BN_EPS   1e-5f
#define DEG_CAP  64

// ---------------- scratch (device globals; no allocation allowed) ----------
__device__ float  d_proj[N_NODES * DIM];
__device__ float  d_hA[N_NODES * DIM];
__device__ float  d_hB[N_NODES * DIM];
__device__ double d_stat[3 * 2 * DIM];   // per layer: [sums(32), sumsq(32)]
__device__ float  d_t1[N_GRAPHS * H1];
__device__ float  d_t2[N_GRAPHS * H2];
__device__ float  d_AB[2 * T_DIM];
__device__ int    d_deg[N_NODES];        // zero at load; re-zeroed by k_tail
__device__ int    d_adj[N_NODES * DEG_CAP];
__device__ int    d_goff[N_GRAPHS + 1];

#define EDGE_BLOCKS  ((N_EDGES + 255) / 256)             // 3907
#define GOFF_BLOCKS  ((N_GRAPHS + 1 + 255) / 256)        // 9
#define T_BLOCKS     (N_GRAPHS / 16)                     // 128
#define AGG_GRID     1184                                // 8 * 148 SMs (one wave)
#define PROJ_BLOCKS  1024

// ---------------- build: adjacency + goff + target BN stats + stat zeroing
__global__ void k_build(const int* __restrict__ src, const int* __restrict__ dst,
                        int* __restrict__ deg, int* __restrict__ adj,
                        const int* __restrict__ batch, int* __restrict__ goff,
                        const float* __restrict__ target,
                        const float* __restrict__ g1, const float* __restrict__ be1,
                        float* __restrict__ AB,
                        double* __restrict__ stat) {
    int b = blockIdx.x;
    if (b < EDGE_BLOCKS) {
        int i = b * 256 + threadIdx.x;
        if (i < N_EDGES) {
            int d = dst[i];
            int c = atomicAdd(&deg[d], 1);
            if (c < DEG_CAP) adj[d * DEG_CAP + c] = src[i];
        }
        return;
    }
    if (b < EDGE_BLOCKS + GOFF_BLOCKS) {
        int g = (b - EDGE_BLOCKS) * 256 + threadIdx.x;
        if (g > N_GRAPHS) return;
        int lo = 0, hi = N_NODES;
        while (lo < hi) { int mid = (lo + hi) >> 1; if (batch[mid] < g) lo = mid + 1; else hi = mid; }
        goff[g] = lo;
        return;
    }
    if (b < EDGE_BLOCKS + GOFF_BLOCKS + 1) {
        if (threadIdx.x < 3 * 2 * DIM) stat[threadIdx.x] = 0.0;
        return;
    }
    // target BN stats: one block per column
    int c = b - EDGE_BLOCKS - GOFF_BLOCKS - 1;
    float s = 0.f, q = 0.f;
    for (int r = threadIdx.x; r < N_GRAPHS; r += blockDim.x) {
        float v = target[r * T_DIM + c];
        s += v;
        q = fmaf(v, v, q);
    }
    __shared__ float ssm[256], sqm[256];
    ssm[threadIdx.x] = s; sqm[threadIdx.x] = q;
    __syncthreads();
    for (int st = 128; st > 0; st >>= 1) {
        if (threadIdx.x < st) { ssm[threadIdx.x] += ssm[threadIdx.x + st]; sqm[threadIdx.x] += sqm[threadIdx.x + st]; }
        __syncthreads();
    }
    if (threadIdx.x == 0) {
        float m = ssm[0] / (float)N_GRAPHS;
        float v = sqm[0] / (float)N_GRAPHS - m * m;
        float inv = rsqrtf(v + BN_EPS);
        float A = g1[c] * inv;
        AB[c]         = A;
        AB[T_DIM + c] = be1[c] - m * A;
    }
}

// ---------------- node kernels ----------------------------------------------

// proj = x @ W  (x: [N,78], W: [78,32]) ; one warp per node, grid-stride
__global__ void k_proj_in(const float* __restrict__ x,
                          const float* __restrict__ W,
                          float* __restrict__ out) {
    __shared__ float Ws[F_IN * DIM];
    for (int i = threadIdx.x; i < F_IN * DIM; i += blockDim.x) Ws[i] = W[i];
    __syncthreads();
    int lane = threadIdx.x & 31;
    int gwarp = (blockIdx.x * blockDim.x + threadIdx.x) >> 5;
    const int nwarps = (PROJ_BLOCKS * 256) >> 5;
    for (int n = gwarp; n < N_NODES; n += nwarps) {
        const float* xr = x + (size_t)n * F_IN;
        float r0 = xr[lane];
        float r1 = xr[32 + lane];
        float r2 = (lane < F_IN - 64) ? xr[64 + lane] : 0.f;
        float acc = 0.f;
        #pragma unroll
        for (int k = 0; k < 32; k++)
            acc = fmaf(__shfl_sync(0xffffffffu, r0, k), Ws[k * DIM + lane], acc);
        #pragma unroll
        for (int k = 0; k < 32; k++)
            acc = fmaf(__shfl_sync(0xffffffffu, r1, k), Ws[(32 + k) * DIM + lane], acc);
        #pragma unroll
        for (int k = 0; k < F_IN - 64; k++)
            acc = fmaf(__shfl_sync(0xffffffffu, r2, k), Ws[(64 + k) * DIM + lane], acc);
        out[n * DIM + lane] = acc;
    }
}

// Target-branch blocks shared by both agg kernels (TP: 1=t1 GEMM, 2=t2 softmax)
template <int TP>
__device__ __forceinline__ void target_branch(int tb,
                          const float* __restrict__ tin,
                          const float* __restrict__ AB,
                          const float* __restrict__ Wt,
                          const float* __restrict__ bt,
                          float* __restrict__ tout) {
    if (TP == 1) {
        __shared__ float tn[T_DIM];
        for (int rr = 0; rr < 16; rr++) {
            int row = tb * 16 + rr;
            __syncthreads();
            for (int c = threadIdx.x; c < T_DIM; c += 256)
                tn[c] = fmaf(tin[row * T_DIM + c], AB[c], AB[T_DIM + c]);
            __syncthreads();
            for (int j = threadIdx.x; j < H1; j += 256) {
                float acc = bt[j];
                #pragma unroll 4
                for (int c = 0; c < T_DIM; c++) acc = fmaf(tn[c], Wt[c * H1 + j], acc);
                tout[row * H1 + j] = acc;
            }
        }
    } else {
        __shared__ float t1s[H1];
        __shared__ float red2[4];
        int j = threadIdx.x;
        bool act = j < 128;
        int wid = j >> 5, lane = j & 31;
        for (int rr = 0; rr < 16; rr++) {
            int row = tb * 16 + rr;
            __syncthreads();
            for (int c = j; c < H1; c += 256) t1s[c] = tin[row * H1 + c];
            __syncthreads();
            float acc = 0.f;
            if (act) {
                acc = bt[j];
                #pragma unroll 2
                for (int c = 0; c < H1; c++) acc = fmaf(t1s[c], Wt[c * H2 + j], acc);
                float m = acc;
                for (int o = 16; o > 0; o >>= 1) m = fmaxf(m, __shfl_xor_sync(0xffffffffu, m, o));
                if (lane == 0) red2[wid] = m;
            }
            __syncthreads();
            float e = 0.f, s = 0.f;
            if (act) {
                float mm = fmaxf(fmaxf(red2[0], red2[1]), fmaxf(red2[2], red2[3]));
                e = expf(acc - mm);
                s = e;
                for (int o = 16; o > 0; o >>= 1) s += __shfl_xor_sync(0xffffffffu, s, o);
            }
            __syncthreads();
            if (act && lane == 0) red2[wid] = s;
            __syncthreads();
            if (act) {
                float ssum = red2[0] + red2[1] + red2[2] + red2[3];
                tout[row * H2 + j] = e / ssum;
            }
        }
    }
}

// 8-way batched gather: issue 8 independent LDGs per batch, then reduce.
__device__ __forceinline__ float gather8(const float* __restrict__ base,
                                         int idx, int cnt, int lane) {
    float a0 = 0.f, a1 = 0.f, a2 = 0.f, a3 = 0.f;
    int k = 0;
    for (; k + 8 <= cnt; k += 8) {
        int s0 = __shfl_sync(0xffffffffu, idx, k);
        int s1 = __shfl_sync(0xffffffffu, idx, k + 1);
        int s2 = __shfl_sync(0xffffffffu, idx, k + 2);
        int s3 = __shfl_sync(0xffffffffu, idx, k + 3);
        int s4 = __shfl_sync(0xffffffffu, idx, k + 4);
        int s5 = __shfl_sync(0xffffffffu, idx, k + 5);
        int s6 = __shfl_sync(0xffffffffu, idx, k + 6);
        int s7 = __shfl_sync(0xffffffffu, idx, k + 7);
        float t0 = base[s0 * DIM + lane];
        float t1 = base[s1 * DIM + lane];
        float t2 = base[s2 * DIM + lane];
        float t3 = base[s3 * DIM + lane];
        float t4 = base[s4 * DIM + lane];
        float t5 = base[s5 * DIM + lane];
        float t6 = base[s6 * DIM + lane];
        float t7 = base[s7 * DIM + lane];
        a0 += t0; a1 += t1; a2 += t2; a3 += t3;
        a0 += t4; a1 += t5; a2 += t6; a3 += t7;
    }
    if (k + 4 <= cnt) {
        int s0 = __shfl_sync(0xffffffffu, idx, k);
        int s1 = __shfl_sync(0xffffffffu, idx, k + 1);
        int s2 = __shfl_sync(0xffffffffu, idx, k + 2);
        int s3 = __shfl_sync(0xffffffffu, idx, k + 3);
        float t0 = base[s0 * DIM + lane];
        float t1 = base[s1 * DIM + lane];
        float t2 = base[s2 * DIM + lane];
        float t3 = base[s3 * DIM + lane];
        a0 += t0; a1 += t1; a2 += t2; a3 += t3;
        k += 4;
    }
    if (k + 2 <= cnt) {
        int s0 = __shfl_sync(0xffffffffu, idx, k);
        int s1 = __shfl_sync(0xffffffffu, idx, k + 1);
        float t0 = base[s0 * DIM + lane];
        float t1 = base[s1 * DIM + lane];
        a0 += t0; a1 += t1;
        k += 2;
    }
    if (k < cnt)
        a0 += base[__shfl_sync(0xffffffffu, idx, k) * DIM + lane];
    return (a0 + a1) + (a2 + a3);
}

// Layer 1: gather proj + MLP(W11b) + elu + stats ; piggyback t1 (TP=1)
// Simple (non-pipelined) loop; 8 blocks/SM for max residency.
template <int TP>
__global__ void __launch_bounds__(256, 8)
k_agg_mlp1(const float* __restrict__ proj,
           const int* __restrict__ deg,
           const int* __restrict__ adj,
           const float* __restrict__ ba,
           const float* __restrict__ Wb,
           const float* __restrict__ bb,
           float* __restrict__ hout,
           double* __restrict__ stat,
           const float* __restrict__ tin,
           const float* __restrict__ AB,
           const float* __restrict__ Wt,
           const float* __restrict__ bt,
           float* __restrict__ tout) {
    if (TP != 0 && blockIdx.x < T_BLOCKS) {
        target_branch<TP>(blockIdx.x, tin, AB, Wt, bt, tout);
        return;
    }
    const int abid = (TP != 0) ? (blockIdx.x - T_BLOCKS) : blockIdx.x;
    const int nblocks = (TP != 0) ? (gridDim.x - T_BLOCKS) : gridDim.x;
    __shared__ float Ws[DIM * DIM];
    __shared__ float bas[DIM], bbs[DIM];
    __shared__ float red[2 * DIM];
    for (int i = threadIdx.x; i < DIM * DIM; i += blockDim.x) Ws[i] = Wb[i];
    if (threadIdx.x < DIM) { bas[threadIdx.x] = ba[threadIdx.x]; bbs[threadIdx.x] = bb[threadIdx.x]; }
    if (threadIdx.x < 2 * DIM) red[threadIdx.x] = 0.f;
    __syncthreads();
    int lane = threadIdx.x & 31;
    int gwarp = (abid * 256 + threadIdx.x) >> 5;
    const int nwarps = nblocks << 3;
    float lsum = 0.f, lsq = 0.f;
    for (int n = gwarp; n < N_NODES; n += nwarps) {
        int dn = deg[n]; if (dn > DEG_CAP) dn = DEG_CAP;
        const int* an = adj + (size_t)n * DEG_CAP;
        int idxA = (lane < dn) ? an[lane] : 0;
        float z = proj[n * DIM + lane] + bas[lane];
        z += gather8(proj, idxA, dn < 32 ? dn : 32, lane);
        if (dn > 32) {
            int idxB = (lane < dn - 32) ? an[32 + lane] : 0;
            z += gather8(proj, idxB, dn - 32, lane);
        }
        float r = fmaxf(z, 0.f);
        float accA = bbs[lane], accB = 0.f;
        #pragma unroll
        for (int kk = 0; kk < DIM; kk += 2) {
            accA = fmaf(__shfl_sync(0xffffffffu, r, kk),     Ws[kk * DIM + lane],       accA);
            accB = fmaf(__shfl_sync(0xffffffffu, r, kk + 1), Ws[(kk + 1) * DIM + lane], accB);
        }
        float acc = accA + accB;
        float o = (acc > 0.f) ? acc : expm1f(acc);   // elu
        hout[n * DIM + lane] = o;
        lsum += o;
        lsq  = fmaf(o, o, lsq);
    }
    atomicAdd(&red[lane], lsum);
    atomicAdd(&red[DIM + lane], lsq);
    __syncthreads();
    if (threadIdx.x < 2 * DIM)
        atomicAdd(&stat[threadIdx.x], (double)red[threadIdx.x]);
}

// Layers 2/3: gather RAW h, inline BN fold, relu(z@W1f + (1+deg)*badd + b1) @ W2 + b2
template <int TP>
__global__ void __launch_bounds__(256, 8)
k_agg_bn_mlp(const float* __restrict__ h,
             const int* __restrict__ deg,
             const int* __restrict__ adj,
             const double* __restrict__ statp, // prev-layer stats
             const float* __restrict__ W1,
             const float* __restrict__ b1,
             const float* __restrict__ W2,
             const float* __restrict__ b2,
             float* __restrict__ hout,
             double* __restrict__ stat,
             const float* __restrict__ tin,
             const float* __restrict__ AB,
             const float* __restrict__ Wt,
             const float* __restrict__ bt,
             float* __restrict__ tout) {
    if (TP != 0 && blockIdx.x < T_BLOCKS) {
        target_branch<TP>(blockIdx.x, tin, AB, Wt, bt, tout);
        return;
    }
    const int abid = (TP != 0) ? (blockIdx.x - T_BLOCKS) : blockIdx.x;
    const int nblocks = (TP != 0) ? (gridDim.x - T_BLOCKS) : gridDim.x;
    __shared__ float W1s[DIM * DIM];   // diag(sc) @ W1
    __shared__ float W2s[DIM * DIM];
    __shared__ float badds[DIM];       // sh @ W1
    __shared__ float b1s[DIM], b2s[DIM];
    __shared__ float red[2 * DIM];
    if (threadIdx.x < 32) {
        int j = threadIdx.x;
        double m = statp[j] * (1.0 / N_NODES);
        double v = statp[DIM + j] * (1.0 / N_NODES) - m * m;
        float sc = (float)(1.0 / sqrt(v + (double)BN_EPS));
        float sh = (float)(-m) * sc;
        float bacc = 0.f;
        #pragma unroll
        for (int k = 0; k < DIM; k++) {
            float w = W1[k * DIM + j];
            W1s[k * DIM + j] = __shfl_sync(0xffffffffu, sc, k) * w;
            bacc = fmaf(__shfl_sync(0xffffffffu, sh, k), w, bacc);
        }
        badds[j] = bacc;
        b1s[j] = b1[j];
        b2s[j] = b2[j];
    }
    for (int i = threadIdx.x; i < DIM * DIM; i += blockDim.x) W2s[i] = W2[i];
    if (threadIdx.x < 2 * DIM) red[threadIdx.x] = 0.f;
    __syncthreads();
    int lane = threadIdx.x & 31;
    int gwarp = (abid * 256 + threadIdx.x) >> 5;
    const int nwarps = nblocks << 3;
    float lsum = 0.f, lsq = 0.f;
    for (int n = gwarp; n < N_NODES; n += nwarps) {
        int dnT = deg[n];
        int dn = dnT > DEG_CAP ? DEG_CAP : dnT;
        const int* an = adj + (size_t)n * DEG_CAP;
        int idxA = (lane < dn) ? an[lane] : 0;
        float z = h[n * DIM + lane];
        z += gather8(h, idxA, dn < 32 ? dn : 32, lane);
        if (dn > 32) {
            int idxB = (lane < dn - 32) ? an[32 + lane] : 0;
            z += gather8(h, idxB, dn - 32, lane);
        }
        // acc1 = z @ W1f + (1+deg)*badd + b1
        float acc1A = fmaf((float)(1 + dnT), badds[lane], b1s[lane]);
        float acc1B = 0.f;
        #pragma unroll
        for (int kk = 0; kk < DIM; kk += 2) {
            acc1A = fmaf(__shfl_sync(0xffffffffu, z, kk),     W1s[kk * DIM + lane],       acc1A);
            acc1B = fmaf(__shfl_sync(0xffffffffu, z, kk + 1), W1s[(kk + 1) * DIM + lane], acc1B);
        }
        float r = fmaxf(acc1A + acc1B, 0.f);
        float acc2A = b2s[lane], acc2B = 0.f;
        #pragma unroll
        for (int kk = 0; kk < DIM; kk += 2) {
            acc2A = fmaf(__shfl_sync(0xffffffffu, r, kk),     W2s[kk * DIM + lane],       acc2A);
            acc2B = fmaf(__shfl_sync(0xffffffffu, r, kk + 1), W2s[(kk + 1) * DIM + lane], acc2B);
        }
        float o = fmaxf(acc2A + acc2B, 0.f);    // relu
        hout[n * DIM + lane] = o;
        lsum += o;
        lsq  = fmaf(o, o, lsq);
    }
    atomicAdd(&red[lane], lsum);
    atomicAdd(&red[DIM + lane], lsq);
    __syncthreads();
    if (threadIdx.x < 2 * DIM)
        atomicAdd(&stat[threadIdx.x], (double)red[threadIdx.x]);
}

// Fused graph tail: inline layer-3 BN stats + pool + g2 + head; also re-zeroes deg.
__global__ void k_tail(const float* __restrict__ h,
                       const double* __restrict__ statp,
                       const int* __restrict__ goff,
                       const float* __restrict__ Wn2, const float* __restrict__ bn2b,
                       const float* __restrict__ t2,
                       const float* __restrict__ W4, const float* __restrict__ b4,
                       const float* __restrict__ W5, const float* __restrict__ b5,
                       float* __restrict__ outg,
                       float* __restrict__ out,
                       int* __restrict__ deg) {
    __shared__ float ss_s[2 * DIM];
    __shared__ float pacc[4][DIM];
    __shared__ float gs[DIM];
    __shared__ float xc[256];
    __shared__ float red[4];
    int b = blockIdx.x;
    int j = threadIdx.x;
    int wid = j >> 5, lane = j & 31;
    int zi = b * 128 + j;
    if (zi < N_NODES) deg[zi] = 0;
    if (j < 32) {
        double m = statp[j] * (1.0 / N_NODES);
        double v = statp[DIM + j] * (1.0 / N_NODES) - m * m;
        float sc = (float)(1.0 / sqrt(v + (double)BN_EPS));
        ss_s[j]       = sc;
        ss_s[DIM + j] = (float)(-m) * sc;
    }
    __syncthreads();
    int s0 = goff[b], s1 = goff[b + 1];
    float acc = 0.f;
    for (int n = s0 + wid; n < s1; n += 4) acc += h[n * DIM + lane];
    pacc[wid][lane] = acc;
    __syncthreads();
    if (wid == 0) {
        float a = pacc[0][lane] + pacc[1][lane] + pacc[2][lane] + pacc[3][lane];
        gs[lane] = fmaf(ss_s[lane], a, ss_s[DIM + lane] * (float)(s1 - s0));
    }
    __syncthreads();
    float a2 = bn2b[j];
    #pragma unroll
    for (int k = 0; k < DIM; k++) a2 = fmaf(gs[k], Wn2[k * H2 + j], a2);
    float g2v = fmaxf(a2, 0.f);
    outg[b * H2 + j] = g2v;
    xc[j]       = g2v;
    xc[128 + j] = t2[b * H2 + j];
    __syncthreads();
    float a4 = b4[j];
    #pragma unroll 4
    for (int k = 0; k < 256; k++) a4 = fmaf(xc[k], W4[k * H2 + j], a4);
    float y = fmaxf(a4, 0.f);
    float v = y * W5[j];
    for (int o = 16; o > 0; o >>= 1) v += __shfl_xor_sync(0xffffffffu, v, o);
    if (lane == 0) red[wid] = v;
    __syncthreads();
    if (j == 0) {
        float s = red[0] + red[1] + red[2] + red[3] + b5[0];
        out[b] = 1.f / (1.f + expf(-s));
    }
}

// ---------------- launch ----------------------------------------------------

extern "C" void kernel_launch(void* const* d_in, const int* in_sizes, int n_in,
                              void* d_out, int out_size) {
    const float* x       = (const float*)d_in[0];
    const int*   ei      = (const int*)d_in[1];
    const int*   batch   = (const int*)d_in[2];
    const float* target  = (const float*)d_in[3];
    const float* W11a = (const float*)d_in[4];   const float* b11a = (const float*)d_in[5];
    const float* W11b = (const float*)d_in[6];   const float* b11b = (const float*)d_in[7];
    const float* W12a = (const float*)d_in[8];   const float* b12a = (const float*)d_in[9];
    const float* W12b = (const float*)d_in[10];  const float* b12b = (const float*)d_in[11];
    const float* W13a = (const float*)d_in[12];  const float* b13a = (const float*)d_in[13];
    const float* W13b = (const float*)d_in[14];  const float* b13b = (const float*)d_in[15];
    const float* Wn2  = (const float*)d_in[16];  const float* bn2b = (const float*)d_in[17];
    const float* g1   = (const float*)d_in[18];  const float* be1  = (const float*)d_in[19];
    const float* W31  = (const float*)d_in[20];  const float* b31  = (const float*)d_in[21];
    const float* W32  = (const float*)d_in[22];  const float* b32  = (const float*)d_in[23];
    const float* W4   = (const float*)d_in[24];  const float* b4   = (const float*)d_in[25];
    const float* W5   = (const float*)d_in[26];  const float* b5   = (const float*)d_in[27];
    (void)in_sizes; (void)n_in; (void)out_size;

    const int* src = ei;
    const int* dst = ei + N_EDGES;

    float* out  = (float*)d_out;          // [0, 2048): sigmoid out
    float* outg = out + N_GRAPHS;         // [2048, ...): g2 [2048,128]

    void *pProj, *pHA, *pHB, *pStat, *pT1, *pT2, *pAB, *pDeg, *pAdj, *pGoff;
    cudaGetSymbolAddress(&pProj, d_proj);
    cudaGetSymbolAddress(&pHA,   d_hA);
    cudaGetSymbolAddress(&pHB,   d_hB);
    cudaGetSymbolAddress(&pStat, d_stat);
    cudaGetSymbolAddress(&pT1,   d_t1);
    cudaGetSymbolAddress(&pT2,   d_t2);
    cudaGetSymbolAddress(&pAB,   d_AB);
    cudaGetSymbolAddress(&pDeg,  d_deg);
    cudaGetSymbolAddress(&pAdj,  d_adj);
    cudaGetSymbolAddress(&pGoff, d_goff);

    float*  proj = (float*)pProj;
    float*  hA   = (float*)pHA;
    float*  hB   = (float*)pHB;
    double* stat = (double*)pStat;
    float*  t1b  = (float*)pT1;
    float*  t2b  = (float*)pT2;
    float*  ABb  = (float*)pAB;
    int*    deg  = (int*)pDeg;
    int*    adj  = (int*)pAdj;
    int*    goff = (int*)pGoff;

    const int BUILD_BLOCKS = EDGE_BLOCKS + GOFF_BLOCKS + 1 + T_DIM;

    // 1: build adjacency + goff + target BN stats + zero stats
    k_build<<<BUILD_BLOCKS, 256>>>(src, dst, deg, adj, batch, goff, target, g1, be1, ABb, stat);

    // 2: layer-1 input projection (78 -> 32)
    k_proj_in<<<PROJ_BLOCKS, 256>>>(x, W11a, proj);

    // 3: layer 1 (gather proj + W11b + elu) + piggyback t1 (front of grid)
    k_agg_mlp1<1><<<AGG_GRID, 256>>>(proj, deg, adj, b11a, W11b, b11b,
                                     hA, stat, target, ABb, W31, b31, t1b);

    // 4: layer 2 (gather raw hA, BN fold inline) + piggyback t2 (front of grid)
    k_agg_bn_mlp<2><<<AGG_GRID, 256>>>(hA, deg, adj, stat, W12a, b12a, W12b, b12b,
                                       hB, stat + 2 * DIM, t1b, ABb, W32, b32, t2b);

    // 5: layer 3 (gather raw hB, BN fold inline)
    k_agg_bn_mlp<0><<<AGG_GRID, 256>>>(hB, deg, adj, stat + 2 * DIM, W13a, b13a, W13b, b13b,
                                       hA, stat + 4 * DIM, (const float*)0, (const float*)0,
                                       (const float*)0, (const float*)0, (float*)0);

    // 6: fused graph tail (inline layer-3 stats; re-zero deg for next replay)
    k_tail<<<N_GRAPHS, 128>>>(hA, stat + 4 * DIM, goff, Wn2, bn2b, t2b, W4, b4, W5, b5,
                              outg, out, deg);
}